// round 14
// baseline (speedup 1.0000x reference)
#include <cuda_runtime.h>
#include <cuda_fp16.h>
#include <math.h>
#include <stdint.h>

#define Bb 8
#define Cc 64
#define Tt 128
#define Ee 256
#define HID 1024
#define NEGV -1e10f

// ------------------------- device scratch (no allocs) -----------------------
__device__ float d_QW[Cc*HID];                 // W1@q + b_hidden   [64,1024]
__device__ float d_CW[Bb*Tt*HID];              // W2@ctx            [1024 bt][1024 n]
// DENSE fp16 tiles, 32-word (128B, aligned) rows, K=64 per stage:
// W34: [nc 8][s 8][row 128][32]
__device__ __align__(16) uint32_t d_W34[8*8*128*32];
// A:   [bc 512][s 8][row 128][32]
__device__ __align__(16) uint32_t d_A[512*8*128*32];
__device__ float d_G [Bb*Cc*Ee];
__device__ float d_H2[Bb*Cc*HID];
__device__ float d_X [Bb*Cc*Ee];
__device__ float d_POOL[Bb*384];
__device__ float d_WT0[128*256*5];
__device__ float d_WT1[128*256*4];
__device__ float d_WT2[128*256*3];

// ------------------------------- helpers ------------------------------------
__device__ __forceinline__ float fast_tanh(float x) {
    float xc = fminf(fmaxf(x, -20.f), 20.f);
    float e = __expf(2.f * xc);
    return __fdividef(e - 1.f, e + 1.f);
}
__device__ __forceinline__ uint32_t packh(float a0, float a1) {
    __half h0 = __float2half_rn(a0);
    __half h1 = __float2half_rn(a1);
    return ((uint32_t)__half_as_ushort(h1) << 16) | __half_as_ushort(h0);
}
__device__ __forceinline__ void mma16816(float* d, const uint32_t* a,
                                         const uint32_t* b) {
    asm volatile(
        "mma.sync.aligned.m16n8k16.row.col.f32.f16.f16.f32 "
        "{%0,%1,%2,%3}, {%4,%5,%6,%7}, {%8,%9}, {%0,%1,%2,%3};"
        : "+f"(d[0]), "+f"(d[1]), "+f"(d[2]), "+f"(d[3])
        : "r"(a[0]), "r"(a[1]), "r"(a[2]), "r"(a[3]), "r"(b[0]), "r"(b[1]));
}
__device__ __forceinline__ void ldm4(uint32_t* r, uint32_t addr) {
    asm volatile("ldmatrix.sync.aligned.m8n8.x4.shared.b16 {%0,%1,%2,%3}, [%4];"
                 : "=r"(r[0]), "=r"(r[1]), "=r"(r[2]), "=r"(r[3]) : "r"(addr));
}
__device__ __forceinline__ uint32_t smem_u32(const void* p) {
    uint32_t a;
    asm("{ .reg .u64 t; cvta.to.shared.u64 t, %1; cvt.u32.u64 %0, t; }"
        : "=r"(a) : "l"(p));
    return a;
}
#define CPA16(dst, src) \
    asm volatile("cp.async.cg.shared.global [%0], [%1], 16;" \
                 :: "r"(dst), "l"(src))
#define CPA_COMMIT() asm volatile("cp.async.commit_group;")
#define CPA_WAIT(N)  asm volatile("cp.async.wait_group %0;" :: "n"(N))

// ---------------------------------------------------------------------------
// prep: W34 fp16 dense tiles [nc][s][row][32]
// ---------------------------------------------------------------------------
__global__ void k_splitW(const float* __restrict__ Wh)
{
    int idx = blockIdx.x * 256 + threadIdx.x;   // 1024 n * 256 k-pairs
    int n = idx >> 8, kp = idx & 255;
    int k = kp * 2;                              // unified k 0..511
    float w0 = Wh[n * 1024 + 512 + k];
    float w1 = Wh[n * 1024 + 512 + k + 1];
    int nc = n >> 7, row = n & 127, s = k >> 6, w = (k & 63) >> 1;
    d_W34[((nc * 8 + s) * 128 + row) * 32 + w] = packh(w0, w1);
}

// A tiles (dense): s<4 -> |q-ctx| on e chunk s; s in 4..7 -> q*ctx.
__global__ void k_buildA(const float* __restrict__ q, const float* __restrict__ ctx)
{
    int c = blockIdx.x, b = blockIdx.y;
    const float* ctxb = ctx + b * Tt * Ee;
    const float* qr = q + c * 256;
    uint32_t* dst = &d_A[(size_t)(b * 64 + c) * 8 * 4096];
    for (int i = threadIdx.x; i < 16384; i += 256) {
        int s4 = i >> 12;            // e-chunk 0..3
        int r = i & 4095;
        int t = r >> 5, w = r & 31;
        int e = s4 * 64 + 2 * w;
        float2 cv = *(const float2*)&ctxb[t * 256 + e];
        float2 qv = *(const float2*)&qr[e];
        dst[(s4 * 128 + t) * 32 + w] =
            packh(fabsf(qv.x - cv.x), fabsf(qv.y - cv.y));
        dst[((s4 + 4) * 128 + t) * 32 + w] =
            packh(qv.x * cv.x, qv.y * cv.y);
    }
}

// ---------------------------------------------------------------------------
// Fused QW + CW GEMM. blockIdx.y < 16: CW rows; == 16: QW.
// ---------------------------------------------------------------------------
__global__ void k_qw_cw(const float* __restrict__ query,
                        const float* __restrict__ context,
                        const float* __restrict__ Wh,
                        const float* __restrict__ bh)
{
    const float* A; const float* bias; float* Y;
    int M, m0, koff;
    if (blockIdx.y == 16) { A = query;   M = 64;   m0 = 0;              bias = bh;      Y = d_QW; koff = 0; }
    else                  { A = context; M = 1024; m0 = blockIdx.y*64;  bias = nullptr; Y = d_CW; koff = 256; }
    const int N = 1024, K = 256;

    __shared__ float As[16][65];
    __shared__ float Bs[16][65];
    int tid = threadIdx.x;
    int tx = tid & 15, ty = tid >> 4;
    int n0 = blockIdx.x * 64;
    float acc[4][4] = {};
    for (int k0 = 0; k0 < K; k0 += 16) {
        #pragma unroll
        for (int l = 0; l < 4; l++) {
            int id = tid + l * 256;
            int m = id >> 4, kk = id & 15;
            int gm = m0 + m;
            As[kk][m] = (gm < M) ? A[gm * 256 + k0 + kk] : 0.f;
            Bs[kk][m] = Wh[(n0 + m) * 1024 + koff + k0 + kk];
        }
        __syncthreads();
        #pragma unroll
        for (int kk = 0; kk < 16; kk++) {
            float a[4], b[4];
            #pragma unroll
            for (int i = 0; i < 4; i++) a[i] = As[kk][i*16 + ty];
            #pragma unroll
            for (int j = 0; j < 4; j++) b[j] = Bs[kk][j*16 + tx];
            #pragma unroll
            for (int i = 0; i < 4; i++)
                #pragma unroll
                for (int j = 0; j < 4; j++)
                    acc[i][j] += a[i] * b[j];
        }
        __syncthreads();
    }
    #pragma unroll
    for (int i = 0; i < 4; i++) {
        int gm = m0 + i*16 + ty;
        if (gm >= M) continue;
        #pragma unroll
        for (int j = 0; j < 4; j++) {
            int gn = n0 + j*16 + tx;
            float v = acc[i][j];
            if (bias) v += bias[gn];
            Y[gm * N + gn] = v;
        }
    }
}

// Transpose conv weights [f][e][i] -> wT[(e*ks+i)][f]  + pool init (fused)
__global__ void k_wTall(const float* __restrict__ w0, const float* __restrict__ w1,
                        const float* __restrict__ w2)
{
    int idx = blockIdx.x * 256 + threadIdx.x;
    if (idx >= 393216) {
        int p = idx - 393216;
        if (p < Bb * 384) d_POOL[p] = 0.f;
        return;
    }
    const float* w; float* wT; int ks; int local;
    if (idx < 163840)      { w = w0; wT = d_WT0; ks = 5; local = idx; }
    else if (idx < 294912) { w = w1; wT = d_WT1; ks = 4; local = idx - 163840; }
    else                   { w = w2; wT = d_WT2; ks = 3; local = idx - 294912; }
    int f = local / (256 * ks);
    int r = local % (256 * ks);
    wT[r * 128 + f] = w[local];
}

// ---------------------------------------------------------------------------
// mma.sync fused attention. CTA per (b,c), 8 warps (4m x 2n).
// Stage = K=64 (4 kk sub-tiles). Global tiles are DENSE (32-word rows);
// FILL remaps each 16B chunk into the 36-word (144B) padded smem rows.
// ---------------------------------------------------------------------------
#define MATW 4608                // smem: 128 rows x 36 words per matrix
#define STGW (2*MATW)            // A + B
#define ATTN_SMEM ((2*STGW + 128 + 128 + 1024 + 128 + 128 + 128) * 4)

__global__ void __launch_bounds__(256, 2) k_attn_mma(
    const float* __restrict__ ctx, const int* __restrict__ mask,
    const float* __restrict__ Wv)
{
    extern __shared__ __align__(16) uint32_t sm[];
    float* qwS   = (float*)(sm + 2*STGW);           // 128
    float* wvS   = qwS + 128;                       // 128
    float* sred  = wvS + 128;                       // 128*8
    float* score = sred + 1024;                     // 128
    float* attnS = score + 128;                     // 128
    float* red   = attnS + 128;                     // 128

    const int tid = threadIdx.x;
    const int lane = tid & 31, wid = tid >> 5;
    const int g = lane >> 2, tig = lane & 3;
    const int wm = wid & 3, wn = wid >> 2;
    const int c = blockIdx.x, b = blockIdx.y;
    const float* ctxb = ctx + b * Tt * Ee;
    const uint32_t smb = smem_u32(sm);
    const uint32_t* Asrc = &d_A[(size_t)(b * 64 + c) * 8 * 4096];

    float part[4] = {0.f, 0.f, 0.f, 0.f};

    // i in [0,2048): half 0 = A chunks, half 1 = B chunks. 1024 chunks each
    // (128 rows x 8 x 16B). src dense (j*16), dst padded (row*144 + ch*16).
    #define FILL(buf, s) do {                                              \
        uint32_t dA = smb + (buf)*STGW*4;                                  \
        uint32_t dB = dA + MATW*4;                                         \
        const char* sA = (const char*)&Asrc[(s)*4096];                     \
        const char* sB = (const char*)&d_W34[(nc*8 + (s))*4096];           \
        for (int i = tid; i < 2048; i += 256) {                            \
            int half = i >> 10;                                            \
            int j = i & 1023;                                              \
            int row = j >> 3, ch = j & 7;                                  \
            uint32_t dst = (half ? dB : dA) + (uint32_t)row*144 + ch*16;   \
            const char* src = (half ? sB : sA) + (size_t)j*16;             \
            CPA16(dst, src);                                               \
        }                                                                  \
        CPA_COMMIT();                                                      \
    } while (0)

    for (int nc = 0; nc < 8; nc++) {
        float acc[2][8][4];
        #pragma unroll
        for (int i = 0; i < 2; i++)
            #pragma unroll
            for (int j = 0; j < 8; j++)
                #pragma unroll
                for (int r = 0; r < 4; r++) acc[i][j][r] = 0.f;

        FILL(0, 0);

        for (int s = 0; s < 8; s++) {
            int cur = s & 1;
            if (s < 7) {
                FILL(cur ^ 1, s + 1);
                CPA_WAIT(1);
            } else {
                CPA_WAIT(0);
            }
            __syncthreads();

            const uint32_t bA = smb + (cur*STGW) * 4;
            const uint32_t bB = bA + MATW * 4;
            const int tile = lane >> 3;

            #pragma unroll
            for (int kk = 0; kk < 4; kk++) {
                uint32_t ah[2][4];
                #pragma unroll
                for (int ms = 0; ms < 2; ms++) {
                    int row = wm*32 + ms*16 + (lane & 7) + (tile & 1) * 8;
                    uint32_t byt = (uint32_t)row*144 + kk*32 + (tile >> 1)*16;
                    ldm4(ah[ms], bA + byt);
                }
                uint32_t bf[8][2];
                #pragma unroll
                for (int ng = 0; ng < 4; ng++) {
                    int row = wn*64 + (ng*2 + (tile >> 1))*8 + (lane & 7);
                    uint32_t byt = (uint32_t)row*144 + kk*32 + (tile & 1)*16;
                    uint32_t tmp[4];
                    ldm4(tmp, bB + byt);
                    bf[2*ng][0]   = tmp[0]; bf[2*ng][1]   = tmp[1];
                    bf[2*ng+1][0] = tmp[2]; bf[2*ng+1][1] = tmp[3];
                }
                #pragma unroll
                for (int ms = 0; ms < 2; ms++)
                    #pragma unroll
                    for (int nt = 0; nt < 8; nt++)
                        mma16816(acc[ms][nt], ah[ms], bf[nt]);
            }
            __syncthreads();
        }

        // ---- epilogue for this n-chunk ----
        if (tid < 128) {
            qwS[tid] = d_QW[c * 1024 + nc * 128 + tid];
            wvS[tid] = Wv[nc * 128 + tid];
        }
        __syncthreads();

        #pragma unroll
        for (int ms = 0; ms < 2; ms++) {
            int r0 = wm*32 + ms*16 + g;
            const float* cwA = &d_CW[(size_t)(b*128 + r0) * 1024 + nc*128];
            const float* cwB = &d_CW[(size_t)(b*128 + r0 + 8) * 1024 + nc*128];
            #pragma unroll
            for (int nt = 0; nt < 8; nt++) {
                int nl = wn*64 + nt*8 + 2*tig;
                float qw0 = qwS[nl], qw1 = qwS[nl+1];
                float wv0 = wvS[nl], wv1 = wvS[nl+1];
                float2 ca = *(const float2*)&cwA[nl];
                float2 cb = *(const float2*)&cwB[nl];
                float v00 = acc[ms][nt][0] + qw0 + ca.x;
                float v01 = acc[ms][nt][1] + qw1 + ca.y;
                float v10 = acc[ms][nt][2] + qw0 + cb.x;
                float v11 = acc[ms][nt][3] + qw1 + cb.y;
                part[ms*2]   += fast_tanh(v00)*wv0 + fast_tanh(v01)*wv1;
                part[ms*2+1] += fast_tanh(v10)*wv0 + fast_tanh(v11)*wv1;
            }
        }
        __syncthreads();
    }
    #undef FILL

    // ---- scores -> mask -> softmax -> gather ----
    #pragma unroll
    for (int ms = 0; ms < 2; ms++)
        #pragma unroll
        for (int jj = 0; jj < 2; jj++) {
            int row = wm*32 + ms*16 + jj*8 + g;
            sred[row*8 + wn*4 + tig] = part[ms*2 + jj];
        }
    __syncthreads();

    if (tid < 128) {
        float s = 0.f;
        #pragma unroll
        for (int x = 0; x < 8; x++) s += sred[tid*8 + x];
        if (mask[b * 128 + tid] < 1) s = NEGV;
        score[tid] = s;
        red[tid] = s;
    }
    __syncthreads();
    for (int st = 64; st > 0; st >>= 1) {
        if (tid < st) red[tid] = fmaxf(red[tid], red[tid + st]);
        __syncthreads();
    }
    float mx = red[0];
    __syncthreads();
    if (tid < 128) {
        float p = __expf(score[tid] - mx);
        attnS[tid] = p;
        red[tid] = p;
    }
    __syncthreads();
    for (int st = 64; st > 0; st >>= 1) {
        if (tid < st) red[tid] += red[tid + st];
        __syncthreads();
    }
    float inv = 1.f / red[0];
    __syncthreads();

    {
        float acc2 = 0.f;
        for (int tt = 0; tt < 128; tt++)
            acc2 += attnS[tt] * ctxb[tt * 256 + tid];
        d_G[(b * 64 + c) * 256 + tid] = acc2 * inv;
    }
}

// ---------------------------------------------------------------------------
// H2 = tanh( F2(G,q) @ W_hidden[:,256:]^T + QW[m%64] ), F2 built in the loader.
// ---------------------------------------------------------------------------
__global__ void k_h2(const float* __restrict__ query, const float* __restrict__ Wh)
{
    __shared__ float As[16][65];
    __shared__ float Bs[16][65];
    int tid = threadIdx.x;
    int tx = tid & 15, ty = tid >> 4;
    int m0 = blockIdx.y * 64, n0 = blockIdx.x * 64;
    float acc[4][4] = {};
    for (int k0 = 0; k0 < 768; k0 += 16) {
        #pragma unroll
        for (int l = 0; l < 4; l++) {
            int id = tid + l * 256;
            int m = id >> 4, kk = id & 15;
            int gm = m0 + m;
            int k = k0 + kk;
            float v;
            if (k < 256) {
                v = d_G[gm * 256 + k];
            } else {
                int e = k & 255;
                float gv = d_G[gm * 256 + e];
                float qv = query[(gm & 63) * 256 + e];
                v = (k < 512) ? fabsf(qv - gv) : qv * gv;
            }
            As[kk][m] = v;
            Bs[kk][m] = Wh[(n0 + m) * 1024 + 256 + k];
        }
        __syncthreads();
        #pragma unroll
        for (int kk = 0; kk < 16; kk++) {
            float a[4], b[4];
            #pragma unroll
            for (int i = 0; i < 4; i++) a[i] = As[kk][i*16 + ty];
            #pragma unroll
            for (int j = 0; j < 4; j++) b[j] = Bs[kk][j*16 + tx];
            #pragma unroll
            for (int i = 0; i < 4; i++)
                #pragma unroll
                for (int j = 0; j < 4; j++)
                    acc[i][j] += a[i] * b[j];
        }
        __syncthreads();
    }
    #pragma unroll
    for (int i = 0; i < 4; i++) {
        int gm = m0 + i*16 + ty;
        #pragma unroll
        for (int j = 0; j < 4; j++) {
            int gn = n0 + j*16 + tx;
            float v = acc[i][j] + d_QW[(gm & 63) * 1024 + gn];
            d_H2[gm * 1024 + gn] = tanhf(v);
        }
    }
}

// X = H2 @ W_lin^T + b_lin    [512,256], K=1024. grid (4,8).
__global__ void k_x(const float* __restrict__ Wl, const float* __restrict__ bl)
{
    __shared__ float As[16][65];
    __shared__ float Bs[16][65];
    int tid = threadIdx.x;
    int tx = tid & 15, ty = tid >> 4;
    int m0 = blockIdx.y * 64, n0 = blockIdx.x * 64;
    float acc[4][4] = {};
    for (int k0 = 0; k0 < 1024; k0 += 16) {
        #pragma unroll
        for (int l = 0; l < 4; l++) {
            int id = tid + l * 256;
            int m = id >> 4, kk = id & 15;
            As[kk][m] = d_H2[(m0 + m) * 1024 + k0 + kk];
            Bs[kk][m] = Wl[(n0 + m) * 1024 + k0 + kk];
        }
        __syncthreads();
        #pragma unroll
        for (int kk = 0; kk < 16; kk++) {
            float a[4], b[4];
            #pragma unroll
            for (int i = 0; i < 4; i++) a[i] = As[kk][i*16 + ty];
            #pragma unroll
            for (int j = 0; j < 4; j++) b[j] = Bs[kk][j*16 + tx];
            #pragma unroll
            for (int i = 0; i < 4; i++)
                #pragma unroll
                for (int j = 0; j < 4; j++)
                    acc[i][j] += a[i] * b[j];
        }
        __syncthreads();
    }
    #pragma unroll
    for (int i = 0; i < 4; i++) {
        int gm = m0 + i*16 + ty;
        #pragma unroll
        for (int j = 0; j < 4; j++) {
            int gn = n0 + j*16 + tx;
            d_X[gm * 256 + gn] = acc[i][j] + bl[gn];
        }
    }
}

// Conv: weight array selected INSIDE device code.
template<int KS>
__global__ void k_conv2(const float* __restrict__ cb, int ci)
{
    const float* wT = (KS == 5) ? d_WT0 : (KS == 4) ? d_WT1 : d_WT2;
    const int PC_TOT = 64 - KS + 1;
    int b = blockIdx.x, pq = blockIdx.y;
    int P0 = pq * 16;
    int PC = PC_TOT - P0; if (PC > 16) PC = 16;
    if (PC <= 0) return;

    __shared__ float xs2[20][257];
    __shared__ float partS[16][128];
    int tid = threadIdx.x;
    int f = tid & 127, eh = tid >> 7;
    int rows = 64 - P0; if (rows > 20) rows = 20;

    for (int i = tid; i < rows * 256; i += 256) {
        int pl = i >> 8, e = i & 255;
        xs2[pl][e] = d_X[(b*64 + P0 + pl)*256 + e];
    }
    for (int i = tid; i < 16*128; i += 256) ((float*)partS)[i] = 0.f;
    __syncthreads();

    float acc[16];
    #pragma unroll
    for (int p = 0; p < 16; p++) acc[p] = 0.f;

    for (int e = eh*128; e < eh*128 + 128; e++) {
        float wv[KS];
        #pragma unroll
        for (int i = 0; i < KS; i++) wv[i] = __ldg(&wT[(e*KS + i)*128 + f]);
        float xr[16 + KS - 1];
        #pragma unroll
        for (int r = 0; r < 16 + KS - 1; r++)
            xr[r] = (r < rows) ? xs2[r][e] : 0.f;
        #pragma unroll
        for (int p = 0; p < 16; p++)
            #pragma unroll
            for (int i = 0; i < KS; i++)
                acc[p] += xr[p + i] * wv[i];
    }
    #pragma unroll
    for (int p = 0; p < 16; p++) atomicAdd(&partS[p][f], acc[p]);
    __syncthreads();

    if (tid < 128) {
        float bias = cb[tid];
        float best = 0.f;
        for (int p = 0; p < PC; p++)
            best = fmaxf(best, partS[p][tid] + bias);
        atomicMax((int*)&d_POOL[b*384 + ci*128 + tid], __float_as_int(best));
    }
}

__global__ void k_final(const float* __restrict__ Wc, const float* __restrict__ bc,
                        float* __restrict__ out)
{
    int tid = threadIdx.x;
    if (tid >= 320) return;
    int b = tid / 40, ty = tid % 40;
    float s = bc[ty];
    for (int i = 0; i < 384; i++)
        s += d_POOL[b * 384 + i] * Wc[ty * 384 + i];
    out[b * 40 + ty] = s;
}

extern "C" void kernel_launch(void* const* d_in, const int* in_sizes, int n_in,
                              void* d_out, int out_size)
{
    const float* query    = (const float*)d_in[0];
    const float* context  = (const float*)d_in[1];
    const int*   mask     = (const int*)  d_in[2];
    const float* W_hidden = (const float*)d_in[3];
    const float* b_hidden = (const float*)d_in[4];
    const float* W_v      = (const float*)d_in[5];
    // d_in[6] = b_v: softmax-invariant, unused
    const float* W_lin    = (const float*)d_in[7];
    const float* b_lin    = (const float*)d_in[8];
    const float* conv_w0  = (const float*)d_in[9];
    const float* conv_b0  = (const float*)d_in[10];
    const float* conv_w1  = (const float*)d_in[11];
    const float* conv_b1  = (const float*)d_in[12];
    const float* conv_w2  = (const float*)d_in[13];
    const float* conv_b2  = (const float*)d_in[14];
    const float* W_cnn    = (const float*)d_in[15];
    const float* b_cnn    = (const float*)d_in[16];
    float* out = (float*)d_out;

    cudaFuncSetAttribute(k_attn_mma, cudaFuncAttributeMaxDynamicSharedMemorySize,
                         ATTN_SMEM);

    // launch order: buildA is #4 (profiler window)
    k_splitW<<<1024, 256>>>(W_hidden);
    k_wTall<<<1549, 256>>>(conv_w0, conv_w1, conv_w2);   // + pool init
    k_qw_cw<<<dim3(16, 17), 256>>>(query, context, W_hidden, b_hidden);
    k_buildA<<<dim3(64, 8), 256>>>(query, context);      // #4 — PROFILED
    k_attn_mma<<<dim3(64, 8), 256, ATTN_SMEM>>>(context, mask, W_v);
    k_h2<<<dim3(16, 8), 256>>>(query, W_hidden);
    k_x<<<dim3(4, 8), 256>>>(W_lin, b_lin);
    k_conv2<5><<<dim3(8, 4), 256>>>(conv_b0, 0);
    k_conv2<4><<<dim3(8, 4), 256>>>(conv_b1, 1);
    k_conv2<3><<<dim3(8, 4), 256>>>(conv_b2, 2);
    k_final<<<1, 320>>>(W_cnn, b_cnn, out);
}

// round 17
// speedup vs baseline: 1.3621x; 1.3621x over previous
#include <cuda_runtime.h>
#include <cuda_fp16.h>
#include <math.h>
#include <stdint.h>

#define Bb 8
#define Cc 64
#define Tt 128
#define Ee 256
#define HID 1024
#define NEGV -1e10f

// ------------------------- device scratch (no allocs) -----------------------
__device__ float d_QW[Cc*HID];                 // W1@q + b_hidden   [64,1024]
__device__ float d_CW[Bb*Tt*HID];              // W2@ctx            [1024 bt][1024 n]
// fp16 tiles, 36-word rows (32 data + 4 pad), K=64 per stage (R11 layout):
__device__ __align__(16) uint32_t d_W34[8*8*128*36];
__device__ __align__(16) uint32_t d_A[512*8*128*36];
__device__ float d_G [Bb*Cc*Ee];
__device__ float d_H2[Bb*Cc*HID];
__device__ float d_X [Bb*Cc*Ee];
__device__ float d_POOL[Bb*384];
__device__ float d_WT0[128*256*5];
__device__ float d_WT1[128*256*4];
__device__ float d_WT2[128*256*3];

// ------------------------------- helpers ------------------------------------
__device__ __forceinline__ float fast_tanh(float x) {
    float xc = fminf(fmaxf(x, -20.f), 20.f);
    float e = __expf(2.f * xc);
    return __fdividef(e - 1.f, e + 1.f);
}
__device__ __forceinline__ uint32_t packh(float a0, float a1) {
    __half h0 = __float2half_rn(a0);
    __half h1 = __float2half_rn(a1);
    return ((uint32_t)__half_as_ushort(h1) << 16) | __half_as_ushort(h0);
}
__device__ __forceinline__ void mma16816(float* d, const uint32_t* a,
                                         const uint32_t* b) {
    asm volatile(
        "mma.sync.aligned.m16n8k16.row.col.f32.f16.f16.f32 "
        "{%0,%1,%2,%3}, {%4,%5,%6,%7}, {%8,%9}, {%0,%1,%2,%3};"
        : "+f"(d[0]), "+f"(d[1]), "+f"(d[2]), "+f"(d[3])
        : "r"(a[0]), "r"(a[1]), "r"(a[2]), "r"(a[3]), "r"(b[0]), "r"(b[1]));
}
__device__ __forceinline__ void ldm4(uint32_t* r, uint32_t addr) {
    asm volatile("ldmatrix.sync.aligned.m8n8.x4.shared.b16 {%0,%1,%2,%3}, [%4];"
                 : "=r"(r[0]), "=r"(r[1]), "=r"(r[2]), "=r"(r[3]) : "r"(addr));
}
__device__ __forceinline__ uint32_t smem_u32(const void* p) {
    uint32_t a;
    asm("{ .reg .u64 t; cvta.to.shared.u64 t, %1; cvt.u32.u64 %0, t; }"
        : "=r"(a) : "l"(p));
    return a;
}
#define CPA16(dst, src) \
    asm volatile("cp.async.cg.shared.global [%0], [%1], 16;" \
                 :: "r"(dst), "l"(src))
#define CPA_COMMIT() asm volatile("cp.async.commit_group;")
#define CPA_WAIT(N)  asm volatile("cp.async.wait_group %0;" :: "n"(N))

// ---------------------------------------------------------------------------
// PREP megakernel: grid-partitioned independent work.
//  blocks [0,512):    buildA  (per (b,c) A tiles, padded rows)
//  blocks [512,768):  splitW  (W34 fp16 tiles, padded rows)
//  blocks [768,962):  wT transposes + pool init
// ---------------------------------------------------------------------------
__global__ void k_prep(const float* __restrict__ q, const float* __restrict__ ctx,
                       const float* __restrict__ Wh,
                       const float* __restrict__ w0, const float* __restrict__ w1,
                       const float* __restrict__ w2)
{
    int bid = blockIdx.x;
    int tid = threadIdx.x;
    if (bid < 512) {
        // ---- buildA ----
        int c = bid & 63, b = bid >> 6;
        const float* ctxb = ctx + b * Tt * Ee;
        const float* qr = q + c * 256;
        uint32_t* dst = &d_A[(size_t)bid * 8 * 4608];
        for (int i = tid; i < 16384; i += 256) {
            int s4 = i >> 12;
            int r = i & 4095;
            int t = r >> 5, w = r & 31;
            int e = s4 * 64 + 2 * w;
            float2 cv = *(const float2*)&ctxb[t * 256 + e];
            float2 qv = *(const float2*)&qr[e];
            dst[(s4 * 128 + t) * 36 + w] =
                packh(fabsf(qv.x - cv.x), fabsf(qv.y - cv.y));
            dst[((s4 + 4) * 128 + t) * 36 + w] =
                packh(qv.x * cv.x, qv.y * cv.y);
        }
    } else if (bid < 768) {
        // ---- splitW: 262144 elems, 4 per thread ----
        int base = (bid - 512) * 1024;
        #pragma unroll
        for (int l = 0; l < 4; l++) {
            int idx = base + l * 256 + tid;
            int n = idx >> 8, kp = idx & 255;
            int k = kp * 2;
            float v0 = Wh[n * 1024 + 512 + k];
            float v1 = Wh[n * 1024 + 512 + k + 1];
            int nc = n >> 7, row = n & 127, s = k >> 6, w = (k & 63) >> 1;
            d_W34[((nc * 8 + s) * 128 + row) * 36 + w] = packh(v0, v1);
        }
    } else {
        // ---- wT transposes + pool init: 396288 ids, 8 per thread ----
        int base = (bid - 768) * 2048;
        #pragma unroll
        for (int l = 0; l < 8; l++) {
            int idx = base + l * 256 + tid;
            if (idx >= 396288) break;
            if (idx >= 393216) {
                int p = idx - 393216;
                if (p < Bb * 384) d_POOL[p] = 0.f;
                continue;
            }
            const float* w; float* wT; int ks; int local;
            if (idx < 163840)      { w = w0; wT = d_WT0; ks = 5; local = idx; }
            else if (idx < 294912) { w = w1; wT = d_WT1; ks = 4; local = idx - 163840; }
            else                   { w = w2; wT = d_WT2; ks = 3; local = idx - 294912; }
            int f = local / (256 * ks);
            int r = local % (256 * ks);
            wT[r * 128 + f] = w[local];
        }
    }
}

// ---------------------------------------------------------------------------
// Fused QW + CW GEMM. blockIdx.y < 16: CW rows; == 16: QW.
// ---------------------------------------------------------------------------
__global__ void k_qw_cw(const float* __restrict__ query,
                        const float* __restrict__ context,
                        const float* __restrict__ Wh,
                        const float* __restrict__ bh)
{
    const float* A; const float* bias; float* Y;
    int M, m0, koff;
    if (blockIdx.y == 16) { A = query;   M = 64;   m0 = 0;              bias = bh;      Y = d_QW; koff = 0; }
    else                  { A = context; M = 1024; m0 = blockIdx.y*64;  bias = nullptr; Y = d_CW; koff = 256; }
    const int N = 1024, K = 256;

    __shared__ float As[16][65];
    __shared__ float Bs[16][65];
    int tid = threadIdx.x;
    int tx = tid & 15, ty = tid >> 4;
    int n0 = blockIdx.x * 64;
    float acc[4][4] = {};
    for (int k0 = 0; k0 < K; k0 += 16) {
        #pragma unroll
        for (int l = 0; l < 4; l++) {
            int id = tid + l * 256;
            int m = id >> 4, kk = id & 15;
            int gm = m0 + m;
            As[kk][m] = (gm < M) ? A[gm * 256 + k0 + kk] : 0.f;
            Bs[kk][m] = Wh[(n0 + m) * 1024 + koff + k0 + kk];
        }
        __syncthreads();
        #pragma unroll
        for (int kk = 0; kk < 16; kk++) {
            float a[4], b[4];
            #pragma unroll
            for (int i = 0; i < 4; i++) a[i] = As[kk][i*16 + ty];
            #pragma unroll
            for (int j = 0; j < 4; j++) b[j] = Bs[kk][j*16 + tx];
            #pragma unroll
            for (int i = 0; i < 4; i++)
                #pragma unroll
                for (int j = 0; j < 4; j++)
                    acc[i][j] += a[i] * b[j];
        }
        __syncthreads();
    }
    #pragma unroll
    for (int i = 0; i < 4; i++) {
        int gm = m0 + i*16 + ty;
        if (gm >= M) continue;
        #pragma unroll
        for (int j = 0; j < 4; j++) {
            int gn = n0 + j*16 + tx;
            float v = acc[i][j];
            if (bias) v += bias[gn];
            Y[gm * N + gn] = v;
        }
    }
}

// ---------------------------------------------------------------------------
// mma.sync fused attention (R11 config: padded global tiles, flat FILL).
// ---------------------------------------------------------------------------
#define MATW 4608                // 128 rows x 36 words per matrix
#define STGW (2*MATW)            // A + B
#define ATTN_SMEM ((2*STGW + 128 + 128 + 1024 + 128 + 128 + 128) * 4)

__global__ void __launch_bounds__(256, 2) k_attn_mma(
    const float* __restrict__ ctx, const int* __restrict__ mask,
    const float* __restrict__ Wv)
{
    extern __shared__ __align__(16) uint32_t sm[];
    float* qwS   = (float*)(sm + 2*STGW);
    float* wvS   = qwS + 128;
    float* sred  = wvS + 128;
    float* score = sred + 1024;
    float* attnS = score + 128;
    float* red   = attnS + 128;

    const int tid = threadIdx.x;
    const int lane = tid & 31, wid = tid >> 5;
    const int g = lane >> 2, tig = lane & 3;
    const int wm = wid & 3, wn = wid >> 2;
    const int c = blockIdx.x, b = blockIdx.y;
    const float* ctxb = ctx + b * Tt * Ee;
    const uint32_t smb = smem_u32(sm);
    const uint32_t* Asrc = &d_A[(size_t)(b * 64 + c) * 8 * MATW];

    float part[4] = {0.f, 0.f, 0.f, 0.f};

    #define FILL(buf, s) do {                                              \
        uint32_t dA = smb + (buf)*STGW*4;                                  \
        uint32_t dB = dA + MATW*4;                                         \
        const uint4* sA = (const uint4*)&Asrc[(s)*MATW];                   \
        const uint4* sB = (const uint4*)&d_W34[(nc*8 + (s))*MATW];         \
        for (int i = tid; i < 1152; i += 256) {                            \
            CPA16(dA + i*16, sA + i);                                      \
            CPA16(dB + i*16, sB + i);                                      \
        }                                                                  \
        CPA_COMMIT();                                                      \
    } while (0)

    for (int nc = 0; nc < 8; nc++) {
        float acc[2][8][4];
        #pragma unroll
        for (int i = 0; i < 2; i++)
            #pragma unroll
            for (int j = 0; j < 8; j++)
                #pragma unroll
                for (int r = 0; r < 4; r++) acc[i][j][r] = 0.f;

        FILL(0, 0);

        for (int s = 0; s < 8; s++) {
            int cur = s & 1;
            if (s < 7) {
                FILL(cur ^ 1, s + 1);
                CPA_WAIT(1);
            } else {
                CPA_WAIT(0);
            }
            __syncthreads();

            const uint32_t bA = smb + (cur*STGW) * 4;
            const uint32_t bB = bA + MATW * 4;
            const int tile = lane >> 3;

            #pragma unroll
            for (int kk = 0; kk < 4; kk++) {
                uint32_t ah[2][4];
                #pragma unroll
                for (int ms = 0; ms < 2; ms++) {
                    int row = wm*32 + ms*16 + (lane & 7) + (tile & 1) * 8;
                    uint32_t byt = (uint32_t)row*144 + kk*32 + (tile >> 1)*16;
                    ldm4(ah[ms], bA + byt);
                }
                uint32_t bf[8][2];
                #pragma unroll
                for (int ng = 0; ng < 4; ng++) {
                    int row = wn*64 + (ng*2 + (tile >> 1))*8 + (lane & 7);
                    uint32_t byt = (uint32_t)row*144 + kk*32 + (tile & 1)*16;
                    uint32_t tmp[4];
                    ldm4(tmp, bB + byt);
                    bf[2*ng][0]   = tmp[0]; bf[2*ng][1]   = tmp[1];
                    bf[2*ng+1][0] = tmp[2]; bf[2*ng+1][1] = tmp[3];
                }
                #pragma unroll
                for (int ms = 0; ms < 2; ms++)
                    #pragma unroll
                    for (int nt = 0; nt < 8; nt++)
                        mma16816(acc[ms][nt], ah[ms], bf[nt]);
            }
            __syncthreads();
        }

        if (tid < 128) {
            qwS[tid] = d_QW[c * 1024 + nc * 128 + tid];
            wvS[tid] = Wv[nc * 128 + tid];
        }
        __syncthreads();

        #pragma unroll
        for (int ms = 0; ms < 2; ms++) {
            int r0 = wm*32 + ms*16 + g;
            const float* cwA = &d_CW[(size_t)(b*128 + r0) * 1024 + nc*128];
            const float* cwB = &d_CW[(size_t)(b*128 + r0 + 8) * 1024 + nc*128];
            #pragma unroll
            for (int nt = 0; nt < 8; nt++) {
                int nl = wn*64 + nt*8 + 2*tig;
                float qw0 = qwS[nl], qw1 = qwS[nl+1];
                float wv0 = wvS[nl], wv1 = wvS[nl+1];
                float2 ca = *(const float2*)&cwA[nl];
                float2 cb = *(const float2*)&cwB[nl];
                float v00 = acc[ms][nt][0] + qw0 + ca.x;
                float v01 = acc[ms][nt][1] + qw1 + ca.y;
                float v10 = acc[ms][nt][2] + qw0 + cb.x;
                float v11 = acc[ms][nt][3] + qw1 + cb.y;
                part[ms*2]   += fast_tanh(v00)*wv0 + fast_tanh(v01)*wv1;
                part[ms*2+1] += fast_tanh(v10)*wv0 + fast_tanh(v11)*wv1;
            }
        }
        __syncthreads();
    }
    #undef FILL

    #pragma unroll
    for (int ms = 0; ms < 2; ms++)
        #pragma unroll
        for (int jj = 0; jj < 2; jj++) {
            int row = wm*32 + ms*16 + jj*8 + g;
            sred[row*8 + wn*4 + tig] = part[ms*2 + jj];
        }
    __syncthreads();

    if (tid < 128) {
        float s = 0.f;
        #pragma unroll
        for (int x = 0; x < 8; x++) s += sred[tid*8 + x];
        if (mask[b * 128 + tid] < 1) s = NEGV;
        score[tid] = s;
        red[tid] = s;
    }
    __syncthreads();
    for (int st = 64; st > 0; st >>= 1) {
        if (tid < st) red[tid] = fmaxf(red[tid], red[tid + st]);
        __syncthreads();
    }
    float mx = red[0];
    __syncthreads();
    if (tid < 128) {
        float p = __expf(score[tid] - mx);
        attnS[tid] = p;
        red[tid] = p;
    }
    __syncthreads();
    for (int st = 64; st > 0; st >>= 1) {
        if (tid < st) red[tid] += red[tid + st];
        __syncthreads();
    }
    float inv = 1.f / red[0];
    __syncthreads();

    {
        float acc2 = 0.f;
        for (int tt = 0; tt < 128; tt++)
            acc2 += attnS[tt] * ctxb[tt * 256 + tid];
        d_G[(b * 64 + c) * 256 + tid] = acc2 * inv;
    }
}

// ---------------------------------------------------------------------------
// H2 = tanh( F2(G,q) @ W_hidden[:,256:]^T + QW[m%64] )   (PROFILED as #4)
// ---------------------------------------------------------------------------
__global__ void k_h2(const float* __restrict__ query, const float* __restrict__ Wh)
{
    __shared__ float As[16][65];
    __shared__ float Bs[16][65];
    int tid = threadIdx.x;
    int tx = tid & 15, ty = tid >> 4;
    int m0 = blockIdx.y * 64, n0 = blockIdx.x * 64;
    float acc[4][4] = {};
    for (int k0 = 0; k0 < 768; k0 += 16) {
        #pragma unroll
        for (int l = 0; l < 4; l++) {
            int id = tid + l * 256;
            int m = id >> 4, kk = id & 15;
            int gm = m0 + m;
            int k = k0 + kk;
            float v;
            if (k < 256) {
                v = d_G[gm * 256 + k];
            } else {
                int e = k & 255;
                float gv = d_G[gm * 256 + e];
                float qv = query[(gm & 63) * 256 + e];
                v = (k < 512) ? fabsf(qv - gv) : qv * gv;
            }
            As[kk][m] = v;
            Bs[kk][m] = Wh[(n0 + m) * 1024 + 256 + k];
        }
        __syncthreads();
        #pragma unroll
        for (int kk = 0; kk < 16; kk++) {
            float a[4], b[4];
            #pragma unroll
            for (int i = 0; i < 4; i++) a[i] = As[kk][i*16 + ty];
            #pragma unroll
            for (int j = 0; j < 4; j++) b[j] = Bs[kk][j*16 + tx];
            #pragma unroll
            for (int i = 0; i < 4; i++)
                #pragma unroll
                for (int j = 0; j < 4; j++)
                    acc[i][j] += a[i] * b[j];
        }
        __syncthreads();
    }
    #pragma unroll
    for (int i = 0; i < 4; i++) {
        int gm = m0 + i*16 + ty;
        #pragma unroll
        for (int j = 0; j < 4; j++) {
            int gn = n0 + j*16 + tx;
            float v = acc[i][j] + d_QW[(gm & 63) * 1024 + gn];
            d_H2[gm * 1024 + gn] = tanhf(v);
        }
    }
}

// X = H2 @ W_lin^T + b_lin. BM=32, BN=64 -> grid (4,16) = 64 blocks.
__global__ void k_x(const float* __restrict__ Wl, const float* __restrict__ bl)
{
    __shared__ float As[16][33];
    __shared__ float Bs[16][65];
    int tid = threadIdx.x;
    int tx = tid & 15, ty = tid >> 4;
    int m0 = blockIdx.y * 32, n0 = blockIdx.x * 64;
    float acc[2][4] = {};
    for (int k0 = 0; k0 < 1024; k0 += 16) {
        {
            int l = tid >> 8;
            (void)l;
            #pragma unroll
            for (int l2 = 0; l2 < 2; l2++) {
                int id = tid + l2 * 256;
                if (id < 512) {
                    int m = id >> 4, kk = id & 15;
                    As[kk][m] = d_H2[(m0 + m) * 1024 + k0 + kk];
                }
            }
            #pragma unroll
            for (int l2 = 0; l2 < 4; l2++) {
                int id = tid + l2 * 256;
                int m = id >> 4, kk = id & 15;
                Bs[kk][m] = Wl[(n0 + m) * 1024 + k0 + kk];
            }
        }
        __syncthreads();
        #pragma unroll
        for (int kk = 0; kk < 16; kk++) {
            float a[2], b[4];
            #pragma unroll
            for (int i = 0; i < 2; i++) a[i] = As[kk][i*16 + ty];
            #pragma unroll
            for (int j = 0; j < 4; j++) b[j] = Bs[kk][j*16 + tx];
            #pragma unroll
            for (int i = 0; i < 2; i++)
                #pragma unroll
                for (int j = 0; j < 4; j++)
                    acc[i][j] += a[i] * b[j];
        }
        __syncthreads();
    }
    #pragma unroll
    for (int i = 0; i < 2; i++) {
        int gm = m0 + i*16 + ty;
        #pragma unroll
        for (int j = 0; j < 4; j++) {
            int gn = n0 + j*16 + tx;
            d_X[gm * 256 + gn] = acc[i][j] + bl[gn];
        }
    }
}

// ---------------------------------------------------------------------------
// Convs merged into one launch: grid (8, 4, 3), blockIdx.z = conv index.
// ---------------------------------------------------------------------------
struct ConvSmem {
    float xs2[20][257];
    float partS[16][128];
};

template<int KS>
__device__ __forceinline__ void conv_impl(ConvSmem& S, const float* __restrict__ wT,
                                          const float* __restrict__ cb, int ci)
{
    const int PC_TOT = 64 - KS + 1;
    int b = blockIdx.x, pq = blockIdx.y;
    int P0 = pq * 16;
    int PC = PC_TOT - P0; if (PC > 16) PC = 16;
    if (PC <= 0) return;

    int tid = threadIdx.x;
    int f = tid & 127, eh = tid >> 7;
    int rows = 64 - P0; if (rows > 20) rows = 20;

    for (int i = tid; i < rows * 256; i += 256) {
        int pl = i >> 8, e = i & 255;
        S.xs2[pl][e] = d_X[(b*64 + P0 + pl)*256 + e];
    }
    for (int i = tid; i < 16*128; i += 256) ((float*)S.partS)[i] = 0.f;
    __syncthreads();

    float acc[16];
    #pragma unroll
    for (int p = 0; p < 16; p++) acc[p] = 0.f;

    for (int e = eh*128; e < eh*128 + 128; e++) {
        float wv[KS];
        #pragma unroll
        for (int i = 0; i < KS; i++) wv[i] = __ldg(&wT[(e*KS + i)*128 + f]);
        float xr[16 + KS - 1];
        #pragma unroll
        for (int r = 0; r < 16 + KS - 1; r++)
            xr[r] = (r < rows) ? S.xs2[r][e] : 0.f;
        #pragma unroll
        for (int p = 0; p < 16; p++)
            #pragma unroll
            for (int i = 0; i < KS; i++)
                acc[p] += xr[p + i] * wv[i];
    }
    #pragma unroll
    for (int p = 0; p < 16; p++) atomicAdd(&S.partS[p][f], acc[p]);
    __syncthreads();

    if (tid < 128) {
        float bias = cb[tid];
        float best = 0.f;
        for (int p = 0; p < PC; p++)
            best = fmaxf(best, S.partS[p][tid] + bias);
        atomicMax((int*)&d_POOL[b*384 + ci*128 + tid], __float_as_int(best));
    }
}

__global__ void k_convAll(const float* __restrict__ cb0, const float* __restrict__ cb1,
                          const float* __restrict__ cb2)
{
    __shared__ ConvSmem S;
    switch (blockIdx.z) {
        case 0: conv_impl<5>(S, d_WT0, cb0, 0); break;
        case 1: conv_impl<4>(S, d_WT1, cb1, 1); break;
        default: conv_impl<3>(S, d_WT2, cb2, 2); break;
    }
}

__global__ void k_final(const float* __restrict__ Wc, const float* __restrict__ bc,
                        float* __restrict__ out)
{
    int tid = threadIdx.x;
    if (tid >= 320) return;
    int b = tid / 40, ty = tid % 40;
    float s = bc[ty];
    for (int i = 0; i < 384; i++)
        s += d_POOL[b * 384 + i] * Wc[ty * 384 + i];
    out[b * 40 + ty] = s;
}

extern "C" void kernel_launch(void* const* d_in, const int* in_sizes, int n_in,
                              void* d_out, int out_size)
{
    const float* query    = (const float*)d_in[0];
    const float* context  = (const float*)d_in[1];
    const int*   mask     = (const int*)  d_in[2];
    const float* W_hidden = (const float*)d_in[3];
    const float* b_hidden = (const float*)d_in[4];
    const float* W_v      = (const float*)d_in[5];
    // d_in[6] = b_v: softmax-invariant, unused
    const float* W_lin    = (const float*)d_in[7];
    const float* b_lin    = (const float*)d_in[8];
    const float* conv_w0  = (const float*)d_in[9];
    const float* conv_b0  = (const float*)d_in[10];
    const float* conv_w1  = (const float*)d_in[11];
    const float* conv_b1  = (const float*)d_in[12];
    const float* conv_w2  = (const float*)d_in[13];
    const float* conv_b2  = (const float*)d_in[14];
    const float* W_cnn    = (const float*)d_in[15];
    const float* b_cnn    = (const float*)d_in[16];
    float* out = (float*)d_out;

    cudaFuncSetAttribute(k_attn_mma, cudaFuncAttributeMaxDynamicSharedMemorySize,
                         ATTN_SMEM);

    // 1: merged prep (buildA + splitW + wT + pool init)
    k_prep<<<962, 256>>>(query, context, W_hidden, conv_w0, conv_w1, conv_w2);
    // 2: QW + CW
    k_qw_cw<<<dim3(16, 17), 256>>>(query, context, W_hidden, b_hidden);
    // 3: attention
    k_attn_mma<<<dim3(64, 8), 256, ATTN_SMEM>>>(context, mask, W_v);
    // 4: h2 — PROFILED
    k_h2<<<dim3(16, 8), 256>>>(query, W_hidden);
    // 5-7: tail
    k_x<<<dim3(4, 16), 256>>>(W_lin, b_lin);
    k_convAll<<<dim3(8, 4, 3), 256>>>(conv_b0, conv_b1, conv_b2);
    k_final<<<1, 320>>>(W_cnn, b_cnn, out);
}